// round 5
// baseline (speedup 1.0000x reference)
#include <cuda_runtime.h>
#include <cuda_bf16.h>

// Problem constants (fixed dataset shapes)
#define NMAX 100000
#define EMAX 1600000

// -------- scratch (static device globals; no dynamic allocation) --------
__device__ int   g_count[NMAX];     // per-node edge count (histogram)
__device__ int   g_off[NMAX];       // exclusive prefix sum of counts
__device__ int   g_cursor[NMAX];    // atomic fill cursor (init = off)
__device__ int   g_bsum[128];       // block partial sums for the scan
__device__ int   g_col[EMAX];       // CSR: source/col node per edge (grouped by dest)
__device__ float g_eval[EMAX];      // CSR: clipped exp(logit) per edge

// -------- kernel 0: zero the histogram --------
__global__ void zero_counts(int n) {
    int i = blockIdx.x * blockDim.x + threadIdx.x;
    if (i < n) g_count[i] = 0;
}

// -------- kernel 1: histogram of destination nodes --------
__global__ void hist_kernel(const int* __restrict__ ind, int E) {
    int e = blockIdx.x * blockDim.x + threadIdx.x;
    if (e >= E) return;
    int i0 = ind[e];                      // indices[0][e]
    atomicAdd(&g_count[i0], 1);
}

// -------- kernel 2a: per-1024-block exclusive scan, emit block totals --------
__global__ void scan_blocks(int n) {
    __shared__ int sh[1024];
    int t = threadIdx.x;
    int i = blockIdx.x * 1024 + t;
    int v = (i < n) ? g_count[i] : 0;
    sh[t] = v;
    __syncthreads();
    #pragma unroll
    for (int o = 1; o < 1024; o <<= 1) {
        int x = (t >= o) ? sh[t - o] : 0;
        __syncthreads();
        sh[t] += x;
        __syncthreads();
    }
    if (i < n) g_off[i] = sh[t] - v;      // exclusive
    if (t == 1023) g_bsum[blockIdx.x] = sh[t];
}

// -------- kernel 2b: scan the (<=128) block totals in one block --------
__global__ void scan_bsum(int nb) {
    __shared__ int sh[128];
    int t = threadIdx.x;
    int v = (t < nb) ? g_bsum[t] : 0;
    sh[t] = v;
    __syncthreads();
    #pragma unroll
    for (int o = 1; o < 128; o <<= 1) {
        int x = (t >= o) ? sh[t - o] : 0;
        __syncthreads();
        sh[t] += x;
        __syncthreads();
    }
    if (t < nb) g_bsum[t] = sh[t] - v;    // exclusive
}

// -------- kernel 2c: add block bases; init cursors --------
__global__ void add_bases(int n) {
    int i = blockIdx.x * blockDim.x + threadIdx.x;
    if (i >= n) return;
    int o = g_off[i] + g_bsum[i >> 10];
    g_off[i] = o;
    g_cursor[i] = o;
}

// -------- kernel 3: per-edge logits + CSR scatter --------
__global__ void edge_kernel(const float* __restrict__ q,
                            const float* __restrict__ k,
                            const float* __restrict__ eigs,
                            const float* __restrict__ lambda0,
                            const int* __restrict__ ind,
                            int E) {
    int e = blockIdx.x * blockDim.x + threadIdx.x;
    if (e >= E) return;
    int i0 = ind[e];
    int i1 = ind[E + e];

    const float4* q4 = (const float4*)(q + (size_t)i0 * 64);
    const float4* k4 = (const float4*)(k + (size_t)i1 * 64);
    float x = 0.0f;
    #pragma unroll
    for (int j = 0; j < 16; j++) {
        float4 a = q4[j], b = k4[j];
        x += a.x * b.x + a.y * b.y + a.z * b.z + a.w * b.w;
    }

    const float4* ea = (const float4*)(eigs + (size_t)i0 * 32);
    const float4* eb = (const float4*)(eigs + (size_t)i1 * 32);
    float y = 0.0f;
    #pragma unroll
    for (int j = 0; j < 8; j++) {
        float4 a = ea[j], b = eb[j];
        y += a.x * b.x + a.y * b.y + a.z * b.z + a.w * b.w;
    }

    float s  = x * 0.125f + expf(lambda0[0]) * y;   // 1/sqrt(64) = 0.125 exact
    float ev = fminf(expf(s), 5.0f);                // clip(exp,-5,5); exp>0

    int p = atomicAdd(&g_cursor[i0], 1);
    g_col[p]  = i1;
    g_eval[p] = ev;
}

// -------- kernel 4: warp-per-node softmax-normalize + SpMM --------
__global__ void node_kernel(const float* __restrict__ v,
                            float* __restrict__ out,
                            int n) {
    int gw   = (blockIdx.x * blockDim.x + threadIdx.x) >> 5;
    int lane = threadIdx.x & 31;
    if (gw >= n) return;

    int beg = g_off[gw];
    int cnt = g_count[gw];

    // pass 1: denominator (coalesced strided reads of g_eval)
    float denom = 0.0f;
    for (int j = lane; j < cnt; j += 32) denom += g_eval[beg + j];
    #pragma unroll
    for (int o = 16; o; o >>= 1) denom += __shfl_xor_sync(0xFFFFFFFFu, denom, o);
    float inv = (cnt > 0) ? (1.0f / denom) : 0.0f;

    // pass 2: weighted sum of v rows (broadcast col/e, coalesced v row read)
    float a0 = 0.0f, a1 = 0.0f;
    for (int j = 0; j < cnt; j++) {
        int   col = g_col[beg + j];
        float ev  = g_eval[beg + j];
        const float* vr = v + (size_t)col * 64;
        a0 += ev * vr[lane];
        a1 += ev * vr[lane + 32];
    }
    out[(size_t)gw * 64 + lane]      = a0 * inv;
    out[(size_t)gw * 64 + lane + 32] = a1 * inv;
}

extern "C" void kernel_launch(void* const* d_in, const int* in_sizes, int n_in,
                              void* d_out, int out_size) {
    const float* q    = (const float*)d_in[0];
    const float* k    = (const float*)d_in[1];
    const float* v    = (const float*)d_in[2];
    const float* eigs = (const float*)d_in[3];
    const float* l0   = (const float*)d_in[4];
    const int*   ind  = (const int*)d_in[5];
    float*       out  = (float*)d_out;

    int n = in_sizes[0] / 64;     // 100000
    int E = in_sizes[5] / 2;      // 1600000
    int nb = (n + 1023) / 1024;   // scan blocks (98)

    zero_counts<<<(n + 255) / 256, 256>>>(n);
    hist_kernel<<<(E + 255) / 256, 256>>>(ind, E);
    scan_blocks<<<nb, 1024>>>(n);
    scan_bsum<<<1, 128>>>(nb);
    add_bases<<<(n + 255) / 256, 256>>>(n);
    edge_kernel<<<(E + 255) / 256, 256>>>(q, k, eigs, l0, ind, E);
    node_kernel<<<(n * 32 + 255) / 256, 256>>>(v, out, n);
}

// round 6
// speedup vs baseline: 1.7127x; 1.7127x over previous
#include <cuda_runtime.h>
#include <cuda_bf16.h>

// Problem constants (fixed dataset shapes)
#define NMAX 100000
#define EMAX 1600000

// -------- scratch (static device globals; no dynamic allocation) --------
__device__ int g_count[NMAX];     // per-node edge count (histogram)
__device__ int g_off[NMAX];       // start offset per node (contiguous, unordered)
__device__ int g_cursor[NMAX];    // atomic fill cursor (init = off)
__device__ int g_col[EMAX];       // CSR: source/col node per edge (grouped by dest)
__device__ int g_total;           // atomic base for block-ordered offset assignment

// -------- kernel 0: zero histogram + total --------
__global__ void zero_counts(int n) {
    int i = blockIdx.x * blockDim.x + threadIdx.x;
    if (i < n) g_count[i] = 0;
    if (i == 0) g_total = 0;
}

// -------- kernel 1: histogram of destination nodes --------
__global__ void hist_kernel(const int* __restrict__ ind, int E) {
    int e = blockIdx.x * blockDim.x + threadIdx.x;
    if (e >= E) return;
    atomicAdd(&g_count[ind[e]], 1);
}

// -------- kernel 2: block-local exclusive scan + atomic block base --------
// Offsets need only be contiguous per node, not globally sorted, so each
// 1024-block claims a range via one atomicAdd of its total.
__global__ void scan_atomic(int n) {
    __shared__ int sh[1024];
    __shared__ int base;
    int t = threadIdx.x;
    int i = blockIdx.x * 1024 + t;
    int vv = (i < n) ? g_count[i] : 0;
    sh[t] = vv;
    __syncthreads();
    #pragma unroll
    for (int o = 1; o < 1024; o <<= 1) {
        int x = (t >= o) ? sh[t - o] : 0;
        __syncthreads();
        sh[t] += x;
        __syncthreads();
    }
    if (t == 1023) base = atomicAdd(&g_total, sh[1023]);
    __syncthreads();
    if (i < n) {
        int o = sh[t] - vv + base;   // exclusive within block + block base
        g_off[i]    = o;
        g_cursor[i] = o;
    }
}

// -------- kernel 3: scatter source indices into CSR order --------
__global__ void scatter_kernel(const int* __restrict__ ind, int E) {
    int e = blockIdx.x * blockDim.x + threadIdx.x;
    if (e >= E) return;
    int i0 = ind[e];
    int i1 = ind[E + e];
    int p = atomicAdd(&g_cursor[i0], 1);
    g_col[p] = i1;
}

// -------- kernel 4: fused logits + softmax + SpMM, warp per node --------
// q[i0]/eigs[i0] stay in registers for the whole node; every per-edge load
// (k row, eigs row, v row) is a coalesced 128B warp transaction.
__global__ void node_fused(const float* __restrict__ q,
                           const float* __restrict__ k,
                           const float* __restrict__ eigs,
                           const float* __restrict__ v,
                           const float* __restrict__ lambda0,
                           float* __restrict__ out,
                           int n) {
    int gw   = (blockIdx.x * blockDim.x + threadIdx.x) >> 5;
    int lane = threadIdx.x & 31;
    if (gw >= n) return;

    int beg = g_off[gw];
    int cnt = g_count[gw];

    float q0 = q[(size_t)gw * 64 + lane];
    float q1 = q[(size_t)gw * 64 + 32 + lane];
    float eg = eigs[(size_t)gw * 32 + lane];
    float el = expf(lambda0[0]);

    float a0 = 0.0f, a1 = 0.0f, denom = 0.0f;
    for (int j = 0; j < cnt; j++) {
        int col = g_col[beg + j];                   // broadcast load
        size_t cb = (size_t)col * 64;
        float kx0 = k[cb + lane];
        float kx1 = k[cb + 32 + lane];
        float ex  = eigs[(size_t)col * 32 + lane];
        float vx0 = v[cb + lane];
        float vx1 = v[cb + 32 + lane];

        float xp = q0 * kx0 + q1 * kx1;
        float yp = eg * ex;
        #pragma unroll
        for (int o = 16; o; o >>= 1) {              // two interleaved reductions
            xp += __shfl_xor_sync(0xFFFFFFFFu, xp, o);
            yp += __shfl_xor_sync(0xFFFFFFFFu, yp, o);
        }
        float s  = xp * 0.125f + el * yp;           // 1/sqrt(64) = 0.125 exact
        float ev = fminf(expf(s), 5.0f);            // clip(exp,-5,5); exp > 0

        denom += ev;                                 // identical on all lanes
        a0 += ev * vx0;
        a1 += ev * vx1;
    }

    float inv = (cnt > 0) ? (1.0f / denom) : 0.0f;  // denom==0 only if cnt==0
    out[(size_t)gw * 64 + lane]      = a0 * inv;
    out[(size_t)gw * 64 + 32 + lane] = a1 * inv;
}

extern "C" void kernel_launch(void* const* d_in, const int* in_sizes, int n_in,
                              void* d_out, int out_size) {
    const float* q    = (const float*)d_in[0];
    const float* k    = (const float*)d_in[1];
    const float* v    = (const float*)d_in[2];
    const float* eigs = (const float*)d_in[3];
    const float* l0   = (const float*)d_in[4];
    const int*   ind  = (const int*)d_in[5];
    float*       out  = (float*)d_out;

    int n = in_sizes[0] / 64;     // 100000
    int E = in_sizes[5] / 2;      // 1600000
    int nb = (n + 1023) / 1024;

    zero_counts<<<(n + 255) / 256, 256>>>(n);
    hist_kernel<<<(E + 255) / 256, 256>>>(ind, E);
    scan_atomic<<<nb, 1024>>>(n);
    scatter_kernel<<<(E + 255) / 256, 256>>>(ind, E);
    node_fused<<<(n + 7) / 8, 256>>>(q, k, eigs, v, l0, out, n);
}

// round 8
// speedup vs baseline: 2.6396x; 1.5412x over previous
#include <cuda_runtime.h>
#include <cuda_bf16.h>

// Problem constants (fixed dataset shapes)
#define NMAX 100000
#define EMAX 1600000

// -------- scratch (static device globals; no dynamic allocation) --------
__device__ int g_count[NMAX];     // per-node edge count (histogram)
__device__ int g_off[NMAX];       // start offset per node (contiguous, unordered)
__device__ int g_cursor[NMAX];    // atomic fill cursor (init = off)
__device__ int g_col[EMAX];       // CSR: source/col node per edge (grouped by dest)
__device__ int g_total;           // atomic base for block-ordered offset assignment

// -------- kernel 0: zero histogram + total --------
__global__ void zero_counts(int n) {
    int i = blockIdx.x * blockDim.x + threadIdx.x;
    if (i < n) g_count[i] = 0;
    if (i == 0) g_total = 0;
}

// -------- kernel 1: histogram of destination nodes --------
__global__ void hist_kernel(const int* __restrict__ ind, int E) {
    int e = blockIdx.x * blockDim.x + threadIdx.x;
    if (e >= E) return;
    atomicAdd(&g_count[ind[e]], 1);
}

// -------- kernel 2: block-local exclusive scan + atomic block base --------
__global__ void scan_atomic(int n) {
    __shared__ int sh[1024];
    __shared__ int base;
    int t = threadIdx.x;
    int i = blockIdx.x * 1024 + t;
    int vv = (i < n) ? g_count[i] : 0;
    sh[t] = vv;
    __syncthreads();
    #pragma unroll
    for (int o = 1; o < 1024; o <<= 1) {
        int x = (t >= o) ? sh[t - o] : 0;
        __syncthreads();
        sh[t] += x;
        __syncthreads();
    }
    if (t == 1023) base = atomicAdd(&g_total, sh[1023]);
    __syncthreads();
    if (i < n) {
        int o = sh[t] - vv + base;   // exclusive within block + block base
        g_off[i]    = o;
        g_cursor[i] = o;
    }
}

// -------- kernel 3: scatter source indices into CSR order --------
__global__ void scatter_kernel(const int* __restrict__ ind, int E) {
    int e = blockIdx.x * blockDim.x + threadIdx.x;
    if (e >= E) return;
    int i0 = ind[e];
    int i1 = ind[E + e];
    int p = atomicAdd(&g_cursor[i0], 1);
    g_col[p] = i1;
}

// -------- kernel 4: fused logits + softmax + SpMM, warp per node --------
// Single fused per-lane partial: z = (0.125*q)·k + (e^λ*eig)·eig → ONE
// 5-step butterfly per edge. float2 loads, unroll-by-2 for SHFL overlap.
__global__ void node_fused(const float2* __restrict__ q2,
                           const float2* __restrict__ k2,
                           const float*  __restrict__ eigs,
                           const float2* __restrict__ v2,
                           const float*  __restrict__ lambda0,
                           float2* __restrict__ out2,
                           int n) {
    int gw   = (blockIdx.x * blockDim.x + threadIdx.x) >> 5;
    int lane = threadIdx.x & 31;
    if (gw >= n) return;

    int beg = g_off[gw];
    int cnt = g_count[gw];

    float2 qv = q2[(size_t)gw * 32 + lane];
    float q0s = qv.x * 0.125f;                      // fold 1/sqrt(64)
    float q1s = qv.y * 0.125f;
    float egl = expf(lambda0[0]) * eigs[(size_t)gw * 32 + lane];  // fold e^λ

    float ax = 0.0f, ay = 0.0f, denom = 0.0f;
    int j = 0;
    for (; j + 1 < cnt; j += 2) {
        int col0 = g_col[beg + j];
        int col1 = g_col[beg + j + 1];
        size_t b0 = (size_t)col0 * 32 + lane;
        size_t b1 = (size_t)col1 * 32 + lane;
        float2 kA = k2[b0], kB = k2[b1];
        float  eA = eigs[b0], eB = eigs[b1];
        float2 vA = v2[b0], vB = v2[b1];

        float z0 = q0s * kA.x + q1s * kA.y + egl * eA;
        float z1 = q0s * kB.x + q1s * kB.y + egl * eB;
        #pragma unroll
        for (int o = 16; o; o >>= 1) {              // two independent chains
            z0 += __shfl_xor_sync(0xFFFFFFFFu, z0, o);
            z1 += __shfl_xor_sync(0xFFFFFFFFu, z1, o);
        }
        float ev0 = fminf(expf(z0), 5.0f);          // clip(exp,-5,5); exp > 0
        float ev1 = fminf(expf(z1), 5.0f);

        denom += ev0 + ev1;
        ax += ev0 * vA.x + ev1 * vB.x;
        ay += ev0 * vA.y + ev1 * vB.y;
    }
    if (j < cnt) {                                  // odd tail
        int col = g_col[beg + j];
        size_t b = (size_t)col * 32 + lane;
        float2 kA = k2[b];
        float  eA = eigs[b];
        float2 vA = v2[b];
        float z = q0s * kA.x + q1s * kA.y + egl * eA;
        #pragma unroll
        for (int o = 16; o; o >>= 1)
            z += __shfl_xor_sync(0xFFFFFFFFu, z, o);
        float ev = fminf(expf(z), 5.0f);
        denom += ev;
        ax += ev * vA.x;
        ay += ev * vA.y;
    }

    float inv = (cnt > 0) ? (1.0f / denom) : 0.0f;  // denom==0 only if cnt==0
    float2 r; r.x = ax * inv; r.y = ay * inv;
    out2[(size_t)gw * 32 + lane] = r;
}

extern "C" void kernel_launch(void* const* d_in, const int* in_sizes, int n_in,
                              void* d_out, int out_size) {
    const float2* q2   = (const float2*)d_in[0];
    const float2* k2   = (const float2*)d_in[1];
    const float2* v2   = (const float2*)d_in[2];
    const float*  eigs = (const float*)d_in[3];
    const float*  l0   = (const float*)d_in[4];
    const int*    ind  = (const int*)d_in[5];
    float2*       out2 = (float2*)d_out;

    int n = in_sizes[0] / 64;     // 100000
    int E = in_sizes[5] / 2;      // 1600000
    int nb = (n + 1023) / 1024;

    zero_counts<<<(n + 255) / 256, 256>>>(n);
    hist_kernel<<<(E + 255) / 256, 256>>>(ind, E);
    scan_atomic<<<nb, 1024>>>(n);
    scatter_kernel<<<(E + 255) / 256, 256>>>(ind, E);
    node_fused<<<(n + 7) / 8, 256>>>(q2, k2, eigs, v2, l0, out2, n);
}

// round 10
// speedup vs baseline: 2.6402x; 1.0003x over previous
#include <cuda_runtime.h>
#include <cuda_bf16.h>

// Problem constants (fixed dataset shapes)
#define NMAX 100000
#define EMAX 1600000

// -------- scratch (static device globals; no dynamic allocation) --------
__device__ int g_count[NMAX];     // per-node edge count (histogram)
__device__ int g_off[NMAX];       // start offset per node (contiguous, unordered)
__device__ int g_rank[EMAX];      // per-edge rank within its destination node
__device__ int g_col[EMAX];       // CSR: source/col node per edge (grouped by dest)
__device__ int g_total;           // atomic base for block-ordered offset assignment

// -------- kernel 0: zero histogram + total --------
__global__ void zero_counts(int n) {
    int i = blockIdx.x * blockDim.x + threadIdx.x;
    if (i < n) g_count[i] = 0;
    if (i == 0) g_total = 0;
}

// -------- kernel 1: histogram + per-edge rank (4 edges/thread, int4) --------
__global__ void hist_kernel(const int* __restrict__ ind, int E) {
    int t = blockIdx.x * blockDim.x + threadIdx.x;
    int e = t * 4;
    if (e + 3 < E) {
        int4 d = *(const int4*)(ind + e);
        int4 r;
        r.x = atomicAdd(&g_count[d.x], 1);
        r.y = atomicAdd(&g_count[d.y], 1);
        r.z = atomicAdd(&g_count[d.z], 1);
        r.w = atomicAdd(&g_count[d.w], 1);
        *(int4*)(g_rank + e) = r;
    } else {
        for (; e < E; e++) g_rank[e] = atomicAdd(&g_count[ind[e]], 1);
    }
}

// -------- kernel 2: block-local exclusive scan + atomic block base --------
__global__ void scan_atomic(int n) {
    __shared__ int sh[1024];
    __shared__ int base;
    int t = threadIdx.x;
    int i = blockIdx.x * 1024 + t;
    int vv = (i < n) ? g_count[i] : 0;
    sh[t] = vv;
    __syncthreads();
    #pragma unroll
    for (int o = 1; o < 1024; o <<= 1) {
        int x = (t >= o) ? sh[t - o] : 0;
        __syncthreads();
        sh[t] += x;
        __syncthreads();
    }
    if (t == 1023) base = atomicAdd(&g_total, sh[1023]);
    __syncthreads();
    if (i < n) g_off[i] = sh[t] - vv + base;   // exclusive in block + base
}

// -------- kernel 3: atomic-free CSR scatter (4 edges/thread, int4) --------
__global__ void scatter_kernel(const int* __restrict__ ind, int E) {
    int t = blockIdx.x * blockDim.x + threadIdx.x;
    int e = t * 4;
    if (e + 3 < E) {
        int4 d = *(const int4*)(ind + e);        // destinations
        int4 s = *(const int4*)(ind + E + e);    // sources
        int4 r = *(const int4*)(g_rank + e);     // ranks
        g_col[g_off[d.x] + r.x] = s.x;
        g_col[g_off[d.y] + r.y] = s.y;
        g_col[g_off[d.z] + r.z] = s.z;
        g_col[g_off[d.w] + r.w] = s.w;
    } else {
        for (; e < E; e++)
            g_col[g_off[ind[e]] + g_rank[e]] = ind[E + e];
    }
}

// -------- kernel 4: fused logits + softmax + SpMM, warp per node --------
// Single fused per-lane partial: z = (0.125*q)·k + (e^λ*eig)·eig → ONE
// 5-step butterfly per edge. float2 loads, unroll-by-2 for SHFL overlap.
__global__ void node_fused(const float2* __restrict__ q2,
                           const float2* __restrict__ k2,
                           const float*  __restrict__ eigs,
                           const float2* __restrict__ v2,
                           const float*  __restrict__ lambda0,
                           float2* __restrict__ out2,
                           int n) {
    int gw   = (blockIdx.x * blockDim.x + threadIdx.x) >> 5;
    int lane = threadIdx.x & 31;
    if (gw >= n) return;

    int beg = g_off[gw];
    int cnt = g_count[gw];

    float2 qv = q2[(size_t)gw * 32 + lane];
    float q0s = qv.x * 0.125f;                      // fold 1/sqrt(64)
    float q1s = qv.y * 0.125f;
    float egl = expf(lambda0[0]) * eigs[(size_t)gw * 32 + lane];  // fold e^λ

    float ax = 0.0f, ay = 0.0f, denom = 0.0f;
    int j = 0;
    for (; j + 1 < cnt; j += 2) {
        int col0 = g_col[beg + j];
        int col1 = g_col[beg + j + 1];
        size_t b0 = (size_t)col0 * 32 + lane;
        size_t b1 = (size_t)col1 * 32 + lane;
        float2 kA = k2[b0], kB = k2[b1];
        float  eA = eigs[b0], eB = eigs[b1];
        float2 vA = v2[b0], vB = v2[b1];

        float z0 = q0s * kA.x + q1s * kA.y + egl * eA;
        float z1 = q0s * kB.x + q1s * kB.y + egl * eB;
        #pragma unroll
        for (int o = 16; o; o >>= 1) {              // two independent chains
            z0 += __shfl_xor_sync(0xFFFFFFFFu, z0, o);
            z1 += __shfl_xor_sync(0xFFFFFFFFu, z1, o);
        }
        float ev0 = fminf(expf(z0), 5.0f);          // clip(exp,-5,5); exp > 0
        float ev1 = fminf(expf(z1), 5.0f);

        denom += ev0 + ev1;
        ax += ev0 * vA.x + ev1 * vB.x;
        ay += ev0 * vA.y + ev1 * vB.y;
    }
    if (j < cnt) {                                  // odd tail
        int col = g_col[beg + j];
        size_t b = (size_t)col * 32 + lane;
        float2 kA = k2[b];
        float  eA = eigs[b];
        float2 vA = v2[b];
        float z = q0s * kA.x + q1s * kA.y + egl * eA;
        #pragma unroll
        for (int o = 16; o; o >>= 1)
            z += __shfl_xor_sync(0xFFFFFFFFu, z, o);
        float ev = fminf(expf(z), 5.0f);
        denom += ev;
        ax += ev * vA.x;
        ay += ev * vA.y;
    }

    float inv = (cnt > 0) ? (1.0f / denom) : 0.0f;  // denom==0 only if cnt==0
    float2 r; r.x = ax * inv; r.y = ay * inv;
    out2[(size_t)gw * 32 + lane] = r;
}

extern "C" void kernel_launch(void* const* d_in, const int* in_sizes, int n_in,
                              void* d_out, int out_size) {
    const float2* q2   = (const float2*)d_in[0];
    const float2* k2   = (const float2*)d_in[1];
    const float2* v2   = (const float2*)d_in[2];
    const float*  eigs = (const float*)d_in[3];
    const float*  l0   = (const float*)d_in[4];
    const int*    ind  = (const int*)d_in[5];
    float2*       out2 = (float2*)d_out;

    int n  = in_sizes[0] / 64;    // 100000
    int E  = in_sizes[5] / 2;     // 1600000
    int nb = (n + 1023) / 1024;
    int t4 = (E + 3) / 4;         // threads for 4-edge kernels

    zero_counts<<<(n + 255) / 256, 256>>>(n);
    hist_kernel<<<(t4 + 255) / 256, 256>>>(ind, E);
    scan_atomic<<<nb, 1024>>>(n);
    scatter_kernel<<<(t4 + 255) / 256, 256>>>(ind, E);
    node_fused<<<(n + 7) / 8, 256>>>(q2, k2, eigs, v2, l0, out2, n);
}